// round 6
// baseline (speedup 1.0000x reference)
#include <cuda_runtime.h>
#include <cstdint>

// Haar DWT2D with SMEM-staged TMA bulk stores.
// Input:  x  (16, 1, 2048, 2048) fp32
// Output: [ll | lh | hl | hh], each (16,1,1024,1024) fp32, concatenated.
//
// CTA (256 threads) = 2 output rows x 1024 cols x 4 subbands:
//   reads 4 input rows x 2048 cols (8x LDG.128/thread, coalesced),
//   computes Haar, stages results in 32KB SMEM,
//   drains via 4x cp.async.bulk (8KB contiguous per subband plane).

#define B_  16
#define H_  2048
#define W_  2048
#define HO  (H_/2)        // 1024
#define WO  (W_/2)        // 1024
#define ROWPAIRS (HO/2)   // 512 CTAs per image
#define PLANE (16u * 1024u * 1024u)

__device__ __forceinline__ float safef(float v) {
    return isfinite(v) ? v : 0.0f;
}

// top=(a0,b0,a1,b1), bot=(c0,d0,c1,d1): two adjacent 2x2 blocks -> subband s pair
__device__ __forceinline__ float2 haar2(float4 top, float4 bot, int s) {
    float a0 = safef(top.x), b0 = safef(top.y), a1 = safef(top.z), b1 = safef(top.w);
    float c0 = safef(bot.x), d0 = safef(bot.y), c1 = safef(bot.z), d1 = safef(bot.w);
    float p0 = a0 + c0, q0 = b0 + d0, r0 = c0 - a0, t0 = d0 - b0;
    float p1 = a1 + c1, q1 = b1 + d1, r1 = c1 - a1, t1 = d1 - b1;
    float2 v;
    switch (s) {
        case 0:  v.x = 0.5f * (p0 + q0); v.y = 0.5f * (p1 + q1); break;
        case 1:  v.x = 0.5f * (q0 - p0); v.y = 0.5f * (q1 - p1); break;
        case 2:  v.x = 0.5f * (r0 + t0); v.y = 0.5f * (r1 + t1); break;
        default: v.x = 0.5f * (t0 - r0); v.y = 0.5f * (t1 - r1); break;
    }
    return v;
}

__global__ __launch_bounds__(256)
void dwt2d_haar_kernel(const float* __restrict__ x, float* __restrict__ out) {
    // smem staging: [subband][outrow 0/1][1024 cols] = 32KB
    __shared__ __align__(128) float stage[4][2][WO];

    const uint32_t blk = blockIdx.x;          // < 8192
    const uint32_t ip  = blk & (ROWPAIRS - 1);
    const uint32_t b   = blk >> 9;
    const uint32_t t   = threadIdx.x;         // 0..255, covers cols 8t..8t+7

    // input rows 4ip..4ip+3, cols 8t..8t+7
    const uint32_t in_off = b * (uint32_t)(H_ * W_) + (4u * ip) * W_ + 8u * t;
    const float4* p = reinterpret_cast<const float4*>(x + in_off);

    float4 r0a = __ldcs(p);
    float4 r0b = __ldcs(p + 1);
    float4 r1a = __ldcs(p + 512);
    float4 r1b = __ldcs(p + 513);
    float4 r2a = __ldcs(p + 1024);
    float4 r2b = __ldcs(p + 1025);
    float4 r3a = __ldcs(p + 1536);
    float4 r3b = __ldcs(p + 1537);

    // compute + stage to smem (STS.128, conflict-free: lane stride 16B)
    #pragma unroll
    for (int s = 0; s < 4; s++) {
        float2 lo = haar2(r0a, r1a, s);
        float2 hi = haar2(r0b, r1b, s);
        float4 v; v.x = lo.x; v.y = lo.y; v.z = hi.x; v.w = hi.y;
        *reinterpret_cast<float4*>(&stage[s][0][4u * t]) = v;
    }
    #pragma unroll
    for (int s = 0; s < 4; s++) {
        float2 lo = haar2(r2a, r3a, s);
        float2 hi = haar2(r2b, r3b, s);
        float4 v; v.x = lo.x; v.y = lo.y; v.z = hi.x; v.w = hi.y;
        *reinterpret_cast<float4*>(&stage[s][1][4u * t]) = v;
    }

    __syncthreads();

    // one thread drains the CTA's output: 4 bulk stores of 8KB contiguous each
    if (t == 0) {
        asm volatile("fence.proxy.async.shared::cta;" ::: "memory");
        const size_t o0 = (size_t)b * (HO * WO) + (size_t)(2u * ip) * WO;
        #pragma unroll
        for (int s = 0; s < 4; s++) {
            uint32_t src;
            asm("{ .reg .u64 tmp; cvta.to.shared.u64 tmp, %1; cvt.u32.u64 %0, tmp; }"
                : "=r"(src) : "l"(&stage[s][0][0]));
            const float* dst = out + (size_t)s * PLANE + o0;
            asm volatile(
                "cp.async.bulk.global.shared::cta.bulk_group [%0], [%1], %2;"
                :: "l"(dst), "r"(src), "n"(2 * WO * 4)
                : "memory");
        }
        asm volatile("cp.async.bulk.commit_group;" ::: "memory");
        asm volatile("cp.async.bulk.wait_group.read 0;" ::: "memory");
    }
    // smem lives until full CTA exit; thread 0's wait guarantees TMA reads done.
}

extern "C" void kernel_launch(void* const* d_in, const int* in_sizes, int n_in,
                              void* d_out, int out_size) {
    const float* x = (const float*)d_in[0];
    float* out = (float*)d_out;

    const int blocks = B_ * ROWPAIRS;   // 8192
    dwt2d_haar_kernel<<<blocks, 256>>>(x, out);
}

// round 7
// speedup vs baseline: 1.0619x; 1.0619x over previous
#include <cuda_runtime.h>
#include <cstdint>

// Haar DWT2D with SMEM-staged TMA bulk stores.
// Input:  x  (16, 1, 2048, 2048) fp32
// Output: [ll | lh | hl | hh], each (16,1,1024,1024) fp32, concatenated.
//
// CTA (256 threads) = 2 output rows x 1024 cols x 4 subbands:
//   reads 4 input rows x 2048 cols (8x LDG.128/thread, coalesced),
//   computes Haar, stages results in 32KB SMEM,
//   drains via 4x cp.async.bulk (8KB contiguous per subband plane).

#define B_  16
#define H_  2048
#define W_  2048
#define HO  (H_/2)        // 1024
#define WO  (W_/2)        // 1024
#define ROWPAIRS (HO/2)   // 512 CTAs per image
#define PLANE (16u * 1024u * 1024u)

__device__ __forceinline__ float safef(float v) {
    return isfinite(v) ? v : 0.0f;
}

// top=(a0,b0,a1,b1), bot=(c0,d0,c1,d1): two adjacent 2x2 blocks -> subband s pair
__device__ __forceinline__ float2 haar2(float4 top, float4 bot, int s) {
    float a0 = safef(top.x), b0 = safef(top.y), a1 = safef(top.z), b1 = safef(top.w);
    float c0 = safef(bot.x), d0 = safef(bot.y), c1 = safef(bot.z), d1 = safef(bot.w);
    float p0 = a0 + c0, q0 = b0 + d0, r0 = c0 - a0, t0 = d0 - b0;
    float p1 = a1 + c1, q1 = b1 + d1, r1 = c1 - a1, t1 = d1 - b1;
    float2 v;
    switch (s) {
        case 0:  v.x = 0.5f * (p0 + q0); v.y = 0.5f * (p1 + q1); break;
        case 1:  v.x = 0.5f * (q0 - p0); v.y = 0.5f * (q1 - p1); break;
        case 2:  v.x = 0.5f * (r0 + t0); v.y = 0.5f * (r1 + t1); break;
        default: v.x = 0.5f * (t0 - r0); v.y = 0.5f * (t1 - r1); break;
    }
    return v;
}

__global__ __launch_bounds__(256)
void dwt2d_haar_kernel(const float* __restrict__ x, float* __restrict__ out) {
    // smem staging: [subband][outrow 0/1][1024 cols] = 32KB
    __shared__ __align__(128) float stage[4][2][WO];

    const uint32_t blk = blockIdx.x;          // < 8192
    const uint32_t ip  = blk & (ROWPAIRS - 1);
    const uint32_t b   = blk >> 9;
    const uint32_t t   = threadIdx.x;         // 0..255, covers cols 8t..8t+7

    // input rows 4ip..4ip+3, cols 8t..8t+7
    const uint32_t in_off = b * (uint32_t)(H_ * W_) + (4u * ip) * W_ + 8u * t;
    const float4* p = reinterpret_cast<const float4*>(x + in_off);

    float4 r0a = __ldcs(p);
    float4 r0b = __ldcs(p + 1);
    float4 r1a = __ldcs(p + 512);
    float4 r1b = __ldcs(p + 513);
    float4 r2a = __ldcs(p + 1024);
    float4 r2b = __ldcs(p + 1025);
    float4 r3a = __ldcs(p + 1536);
    float4 r3b = __ldcs(p + 1537);

    // compute + stage to smem (STS.128, conflict-free: lane stride 16B)
    #pragma unroll
    for (int s = 0; s < 4; s++) {
        float2 lo = haar2(r0a, r1a, s);
        float2 hi = haar2(r0b, r1b, s);
        float4 v; v.x = lo.x; v.y = lo.y; v.z = hi.x; v.w = hi.y;
        *reinterpret_cast<float4*>(&stage[s][0][4u * t]) = v;
    }
    #pragma unroll
    for (int s = 0; s < 4; s++) {
        float2 lo = haar2(r2a, r3a, s);
        float2 hi = haar2(r2b, r3b, s);
        float4 v; v.x = lo.x; v.y = lo.y; v.z = hi.x; v.w = hi.y;
        *reinterpret_cast<float4*>(&stage[s][1][4u * t]) = v;
    }

    __syncthreads();

    // one thread drains the CTA's output: 4 bulk stores of 8KB contiguous each
    if (t == 0) {
        asm volatile("fence.proxy.async.shared::cta;" ::: "memory");
        const size_t o0 = (size_t)b * (HO * WO) + (size_t)(2u * ip) * WO;
        #pragma unroll
        for (int s = 0; s < 4; s++) {
            uint32_t src;
            asm("{ .reg .u64 tmp; cvta.to.shared.u64 tmp, %1; cvt.u32.u64 %0, tmp; }"
                : "=r"(src) : "l"(&stage[s][0][0]));
            const float* dst = out + (size_t)s * PLANE + o0;
            asm volatile(
                "cp.async.bulk.global.shared::cta.bulk_group [%0], [%1], %2;"
                :: "l"(dst), "r"(src), "n"(2 * WO * 4)
                : "memory");
        }
        asm volatile("cp.async.bulk.commit_group;" ::: "memory");
        asm volatile("cp.async.bulk.wait_group.read 0;" ::: "memory");
    }
    // smem lives until full CTA exit; thread 0's wait guarantees TMA reads done.
}

extern "C" void kernel_launch(void* const* d_in, const int* in_sizes, int n_in,
                              void* d_out, int out_size) {
    const float* x = (const float*)d_in[0];
    float* out = (float*)d_out;

    const int blocks = B_ * ROWPAIRS;   // 8192
    dwt2d_haar_kernel<<<blocks, 256>>>(x, out);
}

// round 8
// speedup vs baseline: 1.0897x; 1.0263x over previous
#include <cuda_runtime.h>
#include <cstdint>

// Haar DWT2D, fused single pass, 1x8-output-tile version (MLP=8).
// Input:  x  (16, 1, 2048, 2048) fp32
// Output: [ll | lh | hl | hh], each (16,1,1024,1024) fp32, concatenated.
//
// Each thread: 8 adjacent output columns of one output row
//   = 2 input rows x 16 input cols.
//   8x LDG.128 front-batched (MLP=8, only 2 distinct input rows),
//   8x STG.128 (two adjacent per subband plane).

#define B_  16
#define H_  2048
#define W_  2048
#define HO  (H_/2)            // 1024
#define WO  (W_/2)            // 1024
#define OCTS_PER_ROW (WO/8)   // 128 threads per output row
#define PLANE (16u * 1024u * 1024u)

__device__ __forceinline__ float safef(float v) {
    return isfinite(v) ? v : 0.0f;
}

// top=(a0,b0,a1,b1), bot=(c0,d0,c1,d1): two adjacent 2x2 blocks -> subband s pair
__device__ __forceinline__ float2 haar2(float4 top, float4 bot, int s) {
    float a0 = safef(top.x), b0 = safef(top.y), a1 = safef(top.z), b1 = safef(top.w);
    float c0 = safef(bot.x), d0 = safef(bot.y), c1 = safef(bot.z), d1 = safef(bot.w);
    const float h = 0.5f;
    float2 v;
    switch (s) {
        case 0:  v.x = h*( a0+b0+c0+d0); v.y = h*( a1+b1+c1+d1); break; // ll
        case 1:  v.x = h*(-a0+b0-c0+d0); v.y = h*(-a1+b1-c1+d1); break; // lh
        case 2:  v.x = h*(-a0-b0+c0+d0); v.y = h*(-a1-b1+c1+d1); break; // hl
        default: v.x = h*( a0-b0-c0+d0); v.y = h*( a1-b1-c1+d1); break; // hh
    }
    return v;
}

__global__ __launch_bounds__(256)
void dwt2d_haar_kernel(const float* __restrict__ x, float* __restrict__ out) {
    // tid -> (b, i, j8): j8 indexes a group of 8 output columns
    const uint32_t tid = blockIdx.x * 256u + threadIdx.x;   // < 2^21
    const uint32_t j8 = tid & (OCTS_PER_ROW - 1);
    const uint32_t i  = (tid >> 7) & (HO - 1);              // output row
    const uint32_t b  = tid >> 17;

    // input rows 2i, 2i+1; cols 16*j8 .. 16*j8+15
    const uint32_t in_off = b * (uint32_t)(H_ * W_) + (2u * i) * W_ + 16u * j8;
    const float4* p = reinterpret_cast<const float4*>(x + in_off);
    // row stride = 512 float4s

    // front-batch all 8 loads (MLP=8, 2 distinct rows)
    float4 t0 = __ldcs(p);          // top row, blocks 0,1
    float4 t1 = __ldcs(p + 1);      // top row, blocks 2,3
    float4 t2 = __ldcs(p + 2);      // top row, blocks 4,5
    float4 t3 = __ldcs(p + 3);      // top row, blocks 6,7
    float4 u0 = __ldcs(p + 512);    // bottom row, blocks 0,1
    float4 u1 = __ldcs(p + 513);
    float4 u2 = __ldcs(p + 514);
    float4 u3 = __ldcs(p + 515);

    const uint32_t o = b * (uint32_t)(HO * WO) + i * WO + 8u * j8;
    float* base = out + o;

    #pragma unroll
    for (int s = 0; s < 4; s++) {
        float2 v0 = haar2(t0, u0, s);   // output cols 0,1
        float2 v1 = haar2(t1, u1, s);   // output cols 2,3
        float2 v2 = haar2(t2, u2, s);   // output cols 4,5
        float2 v3 = haar2(t3, u3, s);   // output cols 6,7
        float4 w0; w0.x = v0.x; w0.y = v0.y; w0.z = v1.x; w0.w = v1.y;
        float4 w1; w1.x = v2.x; w1.y = v2.y; w1.z = v3.x; w1.w = v3.y;
        float* dst = base + (uint32_t)s * PLANE;
        __stcs(reinterpret_cast<float4*>(dst),     w0);
        __stcs(reinterpret_cast<float4*>(dst + 4), w1);
    }
}

extern "C" void kernel_launch(void* const* d_in, const int* in_sizes, int n_in,
                              void* d_out, int out_size) {
    const float* x = (const float*)d_in[0];
    float* out = (float*)d_out;

    const int64_t total = (int64_t)B_ * HO * OCTS_PER_ROW;  // 2,097,152 threads
    const int threads = 256;
    const int blocks = (int)(total / threads);              // 8192
    dwt2d_haar_kernel<<<blocks, threads>>>(x, out);
}